// round 13
// baseline (speedup 1.0000x reference)
#include <cuda_runtime.h>

// DynamicLIF persistent kernel for GB300 (sm_103a), round 13.
// Base = R10 (65.0us). CHANGE: per-warp ASYNCHRONOUS publish.
// R10's publish path was: all warps reduce -> __syncthreads -> 8 threads
// gather from smem -> publish (gated on the slowest warp + block barrier +
// smem round-trip). Now each warp's lane 0 publishes its own 8 slice
// partials (two STG.128 into g_part[b][sub][warp][0..7]) + one red.release
// the moment ITS shfl reduction finishes. No intra-block barrier, no smem
// staging on the publish path; rendezvous = max over 128 warps, not 16
// block barriers. The coordinator sums the 8 warp partials per channel in
// the SAME ascending warp order as R10 -> tau bit-identical (rel_err 0.0).
// Count target unchanged (128 releases/batch/step). Sync protocol, packed
// gen|tau release, race-freedom and replay-safety identical to R10.
// mem stays in REGISTERS (R12 proved smem-mem costs ~16us of L1tex traffic).

#define NB 32          // batch
#define NT 8           // time steps
#define NC 128         // channels
#define HW_ 1024       // H*W
#define CR 32          // C / red
#define THREADS 256
#define RPB 8          // channel rows (slices) per block
#define BPB 16         // streaming blocks per batch
#define NSTREAM (NB * BPB)       // 512
#define NBLOCKS (NSTREAM + NB)   // 544 (32 coordinators)
#define PUBS 128       // warp-publishes per batch per step (16 blk x 8 warps)
#define CPAD 64        // 256B stride for g_count (unsigned)
#define SPAD 32        // 256B stride for g_sync (u64)

__device__ float              g_part[NB * BPB * 8 * RPB];  // [b][sub][warp][slice]
__device__ unsigned           g_count[NB * CPAD]; // zero at launch; coord resets at end
__device__ unsigned long long g_sync[NB * SPAD];  // (gen<<32)|tau_bits, monotonic gen

__device__ __forceinline__ unsigned ld_acquire_u32(const unsigned* p) {
    unsigned v;
    asm volatile("ld.acquire.gpu.global.u32 %0, [%1];" : "=r"(v) : "l"(p));
    return v;
}
__device__ __forceinline__ unsigned long long ld_acquire_u64(const unsigned long long* p) {
    unsigned long long v;
    asm volatile("ld.acquire.gpu.global.u64 %0, [%1];" : "=l"(v) : "l"(p));
    return v;
}
__device__ __forceinline__ void st_release_u64(unsigned long long* p, unsigned long long v) {
    asm volatile("st.release.gpu.global.u64 [%0], %1;" :: "l"(p), "l"(v));
}
__device__ __forceinline__ void red_release_add(unsigned* p, unsigned v) {
    asm volatile("red.release.gpu.global.add.u32 [%0], %1;" :: "l"(p), "r"(v));
}

__global__ void __launch_bounds__(THREADS, 4)
lif_kernel(const float* __restrict__ x,
           const float* __restrict__ w1,
           const float* __restrict__ b1,
           const float* __restrict__ w2,
           const float* __restrict__ b2,
           float* __restrict__ out)
{
    const int tid = threadIdx.x;
    const int blk = blockIdx.x;
    const int lane = tid & 31;
    const int warp = tid >> 5;

    // ---------------- coordinator blocks (one per batch) ----------------
    if (blk >= NSTREAM) {
        __shared__ float s_w1t[NC * CR];   // 16 KB, TRANSPOSED: [c][row]
        __shared__ float s_mean[NC];

        const int bb = blk - NSTREAM;
        unsigned*           cnt = &g_count[bb * CPAD];
        unsigned long long* syn = &g_sync[bb * SPAD];

        #pragma unroll
        for (int i = 0; i < (CR * NC) / THREADS; i++) {
            int idx = i * THREADS + tid;
            s_w1t[(idx & 127) * CR + (idx >> 7)] = w1[idx];
        }

        unsigned base_gen = 0;
        if (tid == 0) base_gen = (unsigned)(*(volatile unsigned long long*)syn >> 32);
        __syncthreads();

        #pragma unroll 1
        for (int t = 0; t < NT - 1; t++) {
            if (tid == 0) {
                unsigned tgt = (unsigned)PUBS * (unsigned)(t + 1);
                while (ld_acquire_u32(cnt) < tgt) { }
            }
            __syncthreads();   // acquire by t0 + barrier -> partials visible

            // Channel sum: ascending warp order == R10's s_warp summation
            // -> values and order bit-identical.
            if (tid < NC) {
                const int sub = tid >> 3;     // owning block
                const int r   = tid & 7;      // slice within block
                const float* pp = &g_part[(bb * BPB + sub) * (8 * RPB) + r];
                float s = 0.f;
                #pragma unroll
                for (int w = 0; w < 8; w++) s += __ldcg(pp + w * RPB);
                s_mean[tid] = s * (1.0f / 1024.0f);
            }
            __syncthreads();
            if (tid < CR) {
                float acc = b1[tid];
                #pragma unroll
                for (int c = 0; c < NC; c++)
                    acc = fmaf(s_w1t[c * CR + tid], s_mean[c], acc);
                float e = fmaxf(acc, 0.0f);        // relu
                float p = e * w2[tid];
                p += __shfl_xor_sync(0xffffffffu, p, 16);
                p += __shfl_xor_sync(0xffffffffu, p, 8);
                p += __shfl_xor_sync(0xffffffffu, p, 4);
                p += __shfl_xor_sync(0xffffffffu, p, 2);
                p += __shfl_xor_sync(0xffffffffu, p, 1);
                if (tid == 0) {
                    float z = p + b2[0];
                    float tn = 1.0f / (1.0f + expf(-z));   // sigmoid
                    unsigned long long v =
                        ((unsigned long long)(base_gen + (unsigned)(t + 1)) << 32)
                        | (unsigned long long)__float_as_uint(tn);
                    st_release_u64(syn, v);   // gen + tau in one word
                }
            }
            __syncthreads();
        }
        // All publishes observed -> no publisher remains. Replay-safe reset.
        if (tid == 0) *(volatile unsigned*)cnt = 0;
        return;
    }

    // ---------------- streaming blocks ----------------
    __shared__ float s_tau;

    const int b   = blk >> 4;          // batch
    const int sub = blk & 15;          // sub-block within batch
    unsigned*           const cnt = &g_count[b * CPAD];
    unsigned long long* const syn = &g_sync[b * SPAD];

    // base_gen read precedes this block's first publish (program order), and
    // no release can happen until all 128 warp-publishes -> race-free across
    // startup skew AND graph replays.
    unsigned base_gen = 0;
    if (tid == 0) base_gen = (unsigned)(*(volatile unsigned long long*)syn >> 32);

    float tau = 0.5f;                  // TAU0
    float4 mem[RPB];
    #pragma unroll
    for (int i = 0; i < RPB; i++) mem[i] = make_float4(0.f, 0.f, 0.f, 0.f);

    // This block owns channels [sub*RPB, sub*RPB+RPB) of batch b, all HW.
    const size_t row_base = ((size_t)b * NT * NC + (size_t)sub * RPB) * HW_;
    // This warp's partial slot: g_part[b][sub][warp][0..7].
    float4* const my_part = (float4*)&g_part[(b * BPB + sub) * (8 * RPB) + warp * RPB];

    for (int t = 0; t < NT; t++) {
        const float4* xp = (const float4*)(x   + row_base + (size_t)t * NC * HW_);
        float4*       op = (float4*)      (out + row_base + (size_t)t * NC * HW_);

        // ---- 1) mem = mem*tau + x  (separate mul+add: matches JAX rounding),
        //         per-slice partial sums. Bit-identical to R10. ----
        float part[RPB];
        #pragma unroll
        for (int i = 0; i < RPB; i++) {
            float4 xv = __ldcs(xp + i * THREADS + tid);
            float4 m = mem[i];
            m.x = __fadd_rn(__fmul_rn(m.x, tau), xv.x);
            m.y = __fadd_rn(__fmul_rn(m.y, tau), xv.y);
            m.z = __fadd_rn(__fmul_rn(m.z, tau), xv.z);
            m.w = __fadd_rn(__fmul_rn(m.w, tau), xv.w);
            mem[i] = m;
            part[i] = (m.x + m.y) + (m.z + m.w);
        }

        const bool need_tau = (t < NT - 1);   // last step: no publish/wait

        if (need_tau) {
            // Warp-reduce each slice partial (identical shfl order to R10);
            // reduction leaves the total in every lane.
            #pragma unroll
            for (int i = 0; i < RPB; i++) {
                float v = part[i];
                v += __shfl_xor_sync(0xffffffffu, v, 16);
                v += __shfl_xor_sync(0xffffffffu, v, 8);
                v += __shfl_xor_sync(0xffffffffu, v, 4);
                v += __shfl_xor_sync(0xffffffffu, v, 2);
                v += __shfl_xor_sync(0xffffffffu, v, 1);
                part[i] = v;
            }
            // Per-warp async publish: lane 0 stores 8 partials (2x STG.128)
            // + one release-count. No __syncthreads, no smem.
            if (lane == 0) {
                float4 p0 = make_float4(part[0], part[1], part[2], part[3]);
                float4 p1 = make_float4(part[4], part[5], part[6], part[7]);
                __stcg(my_part,     p0);
                __stcg(my_part + 1, p1);
                red_release_add(cnt, 1u);   // same-thread release orders stores
            }
        }

        // ---- 2) spike + output + soft reset (overlaps coordinator MLP) ----
        #pragma unroll
        for (int i = 0; i < RPB; i++) {
            float4 m = mem[i];
            float4 sp;
            sp.x = (m.x > 1.0f) ? 1.0f : 0.0f;
            sp.y = (m.y > 1.0f) ? 1.0f : 0.0f;
            sp.z = (m.z > 1.0f) ? 1.0f : 0.0f;
            sp.w = (m.w > 1.0f) ? 1.0f : 0.0f;
            __stcs(op + i * THREADS + tid, sp);
            m.x = (m.x > 1.0f) ? 0.0f : m.x;
            m.y = (m.y > 1.0f) ? 0.0f : m.y;
            m.z = (m.z > 1.0f) ? 0.0f : m.z;
            m.w = (m.w > 1.0f) ? 0.0f : m.w;
            mem[i] = m;
        }

        if (!need_tau) break;

        // ---- 3) single poll: generation + tau arrive together ----
        if (tid == 0) {
            unsigned tgt = base_gen + (unsigned)(t + 1);
            unsigned long long v;
            do {
                v = ld_acquire_u64(syn);
            } while ((int)((unsigned)(v >> 32) - tgt) < 0);
            s_tau = __uint_as_float((unsigned)v);
        }
        __syncthreads();
        tau = s_tau;
    }
}

extern "C" void kernel_launch(void* const* d_in, const int* in_sizes, int n_in,
                              void* d_out, int out_size)
{
    const float* x  = (const float*)d_in[0];
    const float* w1 = (const float*)d_in[1];
    const float* b1 = (const float*)d_in[2];
    const float* w2 = (const float*)d_in[3];
    const float* b2 = (const float*)d_in[4];
    float* out = (float*)d_out;

    lif_kernel<<<NBLOCKS, THREADS>>>(x, w1, b1, w2, b2, out);
}

// round 14
// speedup vs baseline: 1.2116x; 1.2116x over previous
#include <cuda_runtime.h>
#include <cstdint>

// DynamicLIF persistent kernel for GB300 (sm_103a), round 14.
// Base = R10 (65.0us). CHANGE: x tiles are loaded by TMA BULK COPY
// (cp.async.bulk, ONE instruction per 32KB tile, mbarrier-completed) into
// smem, issued right after the previous tile's consumption -- so the DRAM
// pull of x[t+1] overlaps the publish + store burst + tau poll window.
// Post-poll phase becomes LDS+FMA (~0.6us) instead of a cold, contended
// 2.4us LDG drain, and the cross-CTA L1tex wavefront-queue spread term
// vanishes (loads bypass the per-thread LSU path entirely).
// Every prior overlap attempt failed by ADDING per-thread LSU ops
// (cp.async R2, prefetch R3/R8, smem-mem R12); bulk TMA is O(1) issue.
// mem stays in REGISTERS. All tau-feeding values/order byte-identical to
// R10 (rel_err 0.0). Sync protocol (count -> coordinator MLP -> packed
// gen|tau release) unchanged.

#define NB 32          // batch
#define NT 8           // time steps
#define NC 128         // channels
#define HW_ 1024       // H*W
#define CR 32          // C / red
#define THREADS 256
#define RPB 8          // channel rows per block
#define BPB 16         // streaming blocks per batch
#define NSTREAM (NB * BPB)       // 512
#define NBLOCKS (NSTREAM + NB)   // 544 (32 coordinators)
#define PUBS (BPB * RPB)         // 128 count-releases per batch per step
#define CPAD 64        // 256B stride for g_count (unsigned)
#define SPAD 32        // 256B stride for g_sync (u64)
#define TILE_BYTES (RPB * THREADS * 16)   // 32768

__device__ float              g_sums[NB * NC];
__device__ unsigned           g_count[NB * CPAD]; // zero at launch; coord resets at end
__device__ unsigned long long g_sync[NB * SPAD];  // (gen<<32)|tau_bits, monotonic gen

__device__ __forceinline__ unsigned ld_acquire_u32(const unsigned* p) {
    unsigned v;
    asm volatile("ld.acquire.gpu.global.u32 %0, [%1];" : "=r"(v) : "l"(p));
    return v;
}
__device__ __forceinline__ unsigned long long ld_acquire_u64(const unsigned long long* p) {
    unsigned long long v;
    asm volatile("ld.acquire.gpu.global.u64 %0, [%1];" : "=l"(v) : "l"(p));
    return v;
}
__device__ __forceinline__ void st_release_u64(unsigned long long* p, unsigned long long v) {
    asm volatile("st.release.gpu.global.u64 [%0], %1;" :: "l"(p), "l"(v));
}
__device__ __forceinline__ void red_release_add(unsigned* p, unsigned v) {
    asm volatile("red.release.gpu.global.add.u32 [%0], %1;" :: "l"(p), "r"(v));
}
__device__ __forceinline__ unsigned smem_u32(const void* p) {
    return (unsigned)__cvta_generic_to_shared(p);
}

__global__ void __launch_bounds__(THREADS, 4)
lif_kernel(const float* __restrict__ x,
           const float* __restrict__ w1,
           const float* __restrict__ b1,
           const float* __restrict__ w2,
           const float* __restrict__ b2,
           float* __restrict__ out)
{
    // Overlaid shared: streaming = 32KB tile + warp partials + tau + mbar;
    // coordinator = 16KB w1t + mean.
    __shared__ __align__(128) char s_raw[TILE_BYTES + 256 + 16];

    const int tid = threadIdx.x;
    const int blk = blockIdx.x;
    const int lane = tid & 31;
    const int warp = tid >> 5;

    // ---------------- coordinator blocks (one per batch) ----------------
    if (blk >= NSTREAM) {
        float* s_w1t  = (float*)s_raw;              // [NC*CR] transposed
        float* s_mean = (float*)(s_raw + 16384);    // [NC]

        const int bb = blk - NSTREAM;
        unsigned*           cnt = &g_count[bb * CPAD];
        unsigned long long* syn = &g_sync[bb * SPAD];

        #pragma unroll
        for (int i = 0; i < (CR * NC) / THREADS; i++) {
            int idx = i * THREADS + tid;
            s_w1t[(idx & 127) * CR + (idx >> 7)] = w1[idx];
        }

        unsigned base_gen = 0;
        if (tid == 0) base_gen = (unsigned)(*(volatile unsigned long long*)syn >> 32);
        __syncthreads();

        #pragma unroll 1
        for (int t = 0; t < NT - 1; t++) {
            if (tid == 0) {
                unsigned tgt = (unsigned)PUBS * (unsigned)(t + 1);
                while (ld_acquire_u32(cnt) < tgt) { }
            }
            __syncthreads();   // acquire by t0 + barrier -> sums visible

            // MLP: values + order byte-identical to R10.
            if (tid < NC)
                s_mean[tid] = __ldcg(&g_sums[bb * NC + tid]) * (1.0f / 1024.0f);
            __syncthreads();
            if (tid < CR) {
                float acc = b1[tid];
                #pragma unroll
                for (int c = 0; c < NC; c++)
                    acc = fmaf(s_w1t[c * CR + tid], s_mean[c], acc);
                float e = fmaxf(acc, 0.0f);        // relu
                float p = e * w2[tid];
                p += __shfl_xor_sync(0xffffffffu, p, 16);
                p += __shfl_xor_sync(0xffffffffu, p, 8);
                p += __shfl_xor_sync(0xffffffffu, p, 4);
                p += __shfl_xor_sync(0xffffffffu, p, 2);
                p += __shfl_xor_sync(0xffffffffu, p, 1);
                if (tid == 0) {
                    float z = p + b2[0];
                    float tn = 1.0f / (1.0f + expf(-z));   // sigmoid
                    unsigned long long v =
                        ((unsigned long long)(base_gen + (unsigned)(t + 1)) << 32)
                        | (unsigned long long)__float_as_uint(tn);
                    st_release_u64(syn, v);   // gen + tau in one word
                }
            }
            __syncthreads();
        }
        if (tid == 0) *(volatile unsigned*)cnt = 0;   // replay-safe reset
        return;
    }

    // ---------------- streaming blocks ----------------
    float4* s_tile = (float4*)s_raw;                            // [RPB*THREADS]
    float (*s_warp)[RPB] = (float(*)[RPB])(s_raw + TILE_BYTES); // [8][RPB]
    float* s_tau = (float*)(s_raw + TILE_BYTES + 240);
    unsigned long long* s_mbar = (unsigned long long*)(s_raw + TILE_BYTES + 248);

    const int b   = blk >> 4;          // batch
    const int sub = blk & 15;          // sub-block within batch
    unsigned*           const cnt = &g_count[b * CPAD];
    unsigned long long* const syn = &g_sync[b * SPAD];
    const unsigned mbar = smem_u32(s_mbar);
    const unsigned tile = smem_u32(s_tile);

    // base_gen read precedes this block's first publish -> race-free.
    unsigned base_gen = 0;
    if (tid == 0) {
        base_gen = (unsigned)(*(volatile unsigned long long*)syn >> 32);
        asm volatile("mbarrier.init.shared.b64 [%0], 1;" :: "r"(mbar) : "memory");
    }
    __syncthreads();

    const size_t row_base = ((size_t)b * NT * NC + (size_t)sub * RPB) * HW_;

    // Prologue: TMA bulk load of x[0] (one instruction).
    if (tid == 0) {
        asm volatile("mbarrier.arrive.expect_tx.shared.b64 _, [%0], %1;"
                     :: "r"(mbar), "r"((unsigned)TILE_BYTES) : "memory");
        asm volatile("cp.async.bulk.shared::cta.global.mbarrier::complete_tx::bytes "
                     "[%0], [%1], %2, [%3];"
                     :: "r"(tile), "l"(x + row_base), "r"((unsigned)TILE_BYTES),
                        "r"(mbar) : "memory");
    }

    float tau = 0.5f;                  // TAU0
    float4 mem[RPB];
    #pragma unroll
    for (int i = 0; i < RPB; i++) mem[i] = make_float4(0.f, 0.f, 0.f, 0.f);

    for (int t = 0; t < NT; t++) {
        float4* op = (float4*)(out + row_base + (size_t)t * NC * HW_);
        const bool need_tau = (t < NT - 1);

        // ---- 0) wait for this step's tile (already complete in steady state) ----
        {
            const unsigned parity = (unsigned)(t & 1);
            unsigned done;
            asm volatile(
                "{\n\t.reg .pred p;\n\t"
                "mbarrier.try_wait.parity.acquire.cta.shared::cta.b64 p, [%1], %2;\n\t"
                "selp.b32 %0, 1, 0, p;\n\t}"
                : "=r"(done) : "r"(mbar), "r"(parity) : "memory");
            if (!done) {
                asm volatile(
                    "{\n\t.reg .pred P1;\n\t"
                    "LW%=:\n\t"
                    "mbarrier.try_wait.parity.acquire.cta.shared::cta.b64 P1, [%0], %1, 0x989680;\n\t"
                    "@P1 bra.uni LD%=;\n\t"
                    "bra.uni LW%=;\n\t"
                    "LD%=:\n\t}"
                    :: "r"(mbar), "r"(parity) : "memory");
            }
        }

        // ---- 1) mem = mem*tau + x (from smem; separate mul+add = JAX
        //         rounding), per-slice partials. Values/order == R10. ----
        float part[RPB];
        #pragma unroll
        for (int i = 0; i < RPB; i++) {
            float4 xv = s_tile[i * THREADS + tid];
            float4 m = mem[i];
            m.x = __fadd_rn(__fmul_rn(m.x, tau), xv.x);
            m.y = __fadd_rn(__fmul_rn(m.y, tau), xv.y);
            m.z = __fadd_rn(__fmul_rn(m.z, tau), xv.z);
            m.w = __fadd_rn(__fmul_rn(m.w, tau), xv.w);
            mem[i] = m;
            part[i] = (m.x + m.y) + (m.z + m.w);
        }

        if (need_tau) {
            #pragma unroll
            for (int i = 0; i < RPB; i++) {
                float v = part[i];
                v += __shfl_xor_sync(0xffffffffu, v, 16);
                v += __shfl_xor_sync(0xffffffffu, v, 8);
                v += __shfl_xor_sync(0xffffffffu, v, 4);
                v += __shfl_xor_sync(0xffffffffu, v, 2);
                v += __shfl_xor_sync(0xffffffffu, v, 1);
                if (lane == 0) s_warp[warp][i] = v;
            }
        }
        __syncthreads();   // tile fully consumed AND s_warp complete

        // ---- 2) kick TMA for x[t+1]: ONE instruction; DRAM pull overlaps
        //         publish + store burst + tau poll ----
        if (t + 1 < NT && tid == 0) {
            asm volatile("mbarrier.arrive.expect_tx.shared.b64 _, [%0], %1;"
                         :: "r"(mbar), "r"((unsigned)TILE_BYTES) : "memory");
            asm volatile("cp.async.bulk.shared::cta.global.mbarrier::complete_tx::bytes "
                         "[%0], [%1], %2, [%3];"
                         :: "r"(tile),
                            "l"(x + row_base + (size_t)(t + 1) * NC * HW_),
                            "r"((unsigned)TILE_BYTES), "r"(mbar) : "memory");
        }

        // ---- 3) publish this block's 8 channel sums (identical to R10) ----
        if (need_tau && tid < RPB) {
            float s = 0.f;
            #pragma unroll
            for (int w = 0; w < 8; w++) s += s_warp[w][tid];
            __stcg(&g_sums[b * NC + sub * RPB + tid], s);
            red_release_add(cnt, 1u);
        }

        // ---- 4) spike + output + soft reset (overlaps TMA + coord MLP) ----
        #pragma unroll
        for (int i = 0; i < RPB; i++) {
            float4 m = mem[i];
            float4 sp;
            sp.x = (m.x > 1.0f) ? 1.0f : 0.0f;
            sp.y = (m.y > 1.0f) ? 1.0f : 0.0f;
            sp.z = (m.z > 1.0f) ? 1.0f : 0.0f;
            sp.w = (m.w > 1.0f) ? 1.0f : 0.0f;
            __stcs(op + i * THREADS + tid, sp);
            m.x = (m.x > 1.0f) ? 0.0f : m.x;
            m.y = (m.y > 1.0f) ? 0.0f : m.y;
            m.z = (m.z > 1.0f) ? 0.0f : m.z;
            m.w = (m.w > 1.0f) ? 0.0f : m.w;
            mem[i] = m;
        }

        if (!need_tau) break;

        // ---- 5) single poll: generation + tau arrive together ----
        if (tid == 0) {
            unsigned tgt = base_gen + (unsigned)(t + 1);
            unsigned long long v;
            do {
                v = ld_acquire_u64(syn);
            } while ((int)((unsigned)(v >> 32) - tgt) < 0);
            *s_tau = __uint_as_float((unsigned)v);
        }
        __syncthreads();
        tau = *s_tau;
    }

    // Invalidate the mbarrier so the next graph replay re-inits cleanly.
    __syncthreads();
    if (tid == 0)
        asm volatile("mbarrier.inval.shared.b64 [%0];" :: "r"(mbar) : "memory");
}

extern "C" void kernel_launch(void* const* d_in, const int* in_sizes, int n_in,
                              void* d_out, int out_size)
{
    const float* x  = (const float*)d_in[0];
    const float* w1 = (const float*)d_in[1];
    const float* b1 = (const float*)d_in[2];
    const float* w2 = (const float*)d_in[3];
    const float* b2 = (const float*)d_in[4];
    float* out = (float*)d_out;

    lif_kernel<<<NBLOCKS, THREADS>>>(x, w1, b1, w2, b2, out);
}

// round 15
// speedup vs baseline: 1.2840x; 1.0598x over previous
#include <cuda_runtime.h>
#include <cstdint>

// DynamicLIF persistent kernel for GB300 (sm_103a), round 15.
// Base = R14 (TMA bulk-load of x tiles; ncu 59.9us). CHANGE: the TMA for
// x[t+1] is issued IMMEDIATELY after the FMA consumption pass (the only
// hazard is "all threads done READING tile t"), before the shfl-reduce.
// Split the single post-pass __syncthreads into two:
//   FMA pass -> sync#1 -> [tid0: TMA t+1] + shfl-reduce -> s_warp write
//   -> sync#2 -> publish -> stores -> poll.
// TMA starts ~0.3us earlier per step, extending the DRAM-overlap window.
// All tau-feeding values/order byte-identical to R10/R14 (rel_err 0.0).
// Sync protocol (count -> coordinator MLP -> packed gen|tau release),
// race-freedom, replay-safety, and smem budget unchanged from R14.

#define NB 32          // batch
#define NT 8           // time steps
#define NC 128         // channels
#define HW_ 1024       // H*W
#define CR 32          // C / red
#define THREADS 256
#define RPB 8          // channel rows per block
#define BPB 16         // streaming blocks per batch
#define NSTREAM (NB * BPB)       // 512
#define NBLOCKS (NSTREAM + NB)   // 544 (32 coordinators)
#define PUBS (BPB * RPB)         // 128 count-releases per batch per step
#define CPAD 64        // 256B stride for g_count (unsigned)
#define SPAD 32        // 256B stride for g_sync (u64)
#define TILE_BYTES (RPB * THREADS * 16)   // 32768

__device__ float              g_sums[NB * NC];
__device__ unsigned           g_count[NB * CPAD]; // zero at launch; coord resets at end
__device__ unsigned long long g_sync[NB * SPAD];  // (gen<<32)|tau_bits, monotonic gen

__device__ __forceinline__ unsigned ld_acquire_u32(const unsigned* p) {
    unsigned v;
    asm volatile("ld.acquire.gpu.global.u32 %0, [%1];" : "=r"(v) : "l"(p));
    return v;
}
__device__ __forceinline__ unsigned long long ld_acquire_u64(const unsigned long long* p) {
    unsigned long long v;
    asm volatile("ld.acquire.gpu.global.u64 %0, [%1];" : "=l"(v) : "l"(p));
    return v;
}
__device__ __forceinline__ void st_release_u64(unsigned long long* p, unsigned long long v) {
    asm volatile("st.release.gpu.global.u64 [%0], %1;" :: "l"(p), "l"(v));
}
__device__ __forceinline__ void red_release_add(unsigned* p, unsigned v) {
    asm volatile("red.release.gpu.global.add.u32 [%0], %1;" :: "l"(p), "r"(v));
}
__device__ __forceinline__ unsigned smem_u32(const void* p) {
    return (unsigned)__cvta_generic_to_shared(p);
}
__device__ __forceinline__ void tma_tile_load(unsigned tile, const float* src, unsigned mbar) {
    asm volatile("mbarrier.arrive.expect_tx.shared.b64 _, [%0], %1;"
                 :: "r"(mbar), "r"((unsigned)TILE_BYTES) : "memory");
    asm volatile("cp.async.bulk.shared::cta.global.mbarrier::complete_tx::bytes "
                 "[%0], [%1], %2, [%3];"
                 :: "r"(tile), "l"(src), "r"((unsigned)TILE_BYTES), "r"(mbar)
                 : "memory");
}

__global__ void __launch_bounds__(THREADS, 4)
lif_kernel(const float* __restrict__ x,
           const float* __restrict__ w1,
           const float* __restrict__ b1,
           const float* __restrict__ w2,
           const float* __restrict__ b2,
           float* __restrict__ out)
{
    // Overlaid shared: streaming = 32KB tile + warp partials + tau + mbar;
    // coordinator = 16KB w1t + mean.
    __shared__ __align__(128) char s_raw[TILE_BYTES + 256 + 16];

    const int tid = threadIdx.x;
    const int blk = blockIdx.x;
    const int lane = tid & 31;
    const int warp = tid >> 5;

    // ---------------- coordinator blocks (one per batch) ----------------
    if (blk >= NSTREAM) {
        float* s_w1t  = (float*)s_raw;              // [NC*CR] transposed
        float* s_mean = (float*)(s_raw + 16384);    // [NC]

        const int bb = blk - NSTREAM;
        unsigned*           cnt = &g_count[bb * CPAD];
        unsigned long long* syn = &g_sync[bb * SPAD];

        #pragma unroll
        for (int i = 0; i < (CR * NC) / THREADS; i++) {
            int idx = i * THREADS + tid;
            s_w1t[(idx & 127) * CR + (idx >> 7)] = w1[idx];
        }

        unsigned base_gen = 0;
        if (tid == 0) base_gen = (unsigned)(*(volatile unsigned long long*)syn >> 32);
        __syncthreads();

        #pragma unroll 1
        for (int t = 0; t < NT - 1; t++) {
            if (tid == 0) {
                unsigned tgt = (unsigned)PUBS * (unsigned)(t + 1);
                while (ld_acquire_u32(cnt) < tgt) { }
            }
            __syncthreads();   // acquire by t0 + barrier -> sums visible

            // MLP: values + order byte-identical to R10.
            if (tid < NC)
                s_mean[tid] = __ldcg(&g_sums[bb * NC + tid]) * (1.0f / 1024.0f);
            __syncthreads();
            if (tid < CR) {
                float acc = b1[tid];
                #pragma unroll
                for (int c = 0; c < NC; c++)
                    acc = fmaf(s_w1t[c * CR + tid], s_mean[c], acc);
                float e = fmaxf(acc, 0.0f);        // relu
                float p = e * w2[tid];
                p += __shfl_xor_sync(0xffffffffu, p, 16);
                p += __shfl_xor_sync(0xffffffffu, p, 8);
                p += __shfl_xor_sync(0xffffffffu, p, 4);
                p += __shfl_xor_sync(0xffffffffu, p, 2);
                p += __shfl_xor_sync(0xffffffffu, p, 1);
                if (tid == 0) {
                    float z = p + b2[0];
                    float tn = 1.0f / (1.0f + expf(-z));   // sigmoid
                    unsigned long long v =
                        ((unsigned long long)(base_gen + (unsigned)(t + 1)) << 32)
                        | (unsigned long long)__float_as_uint(tn);
                    st_release_u64(syn, v);   // gen + tau in one word
                }
            }
            __syncthreads();
        }
        if (tid == 0) *(volatile unsigned*)cnt = 0;   // replay-safe reset
        return;
    }

    // ---------------- streaming blocks ----------------
    float4* s_tile = (float4*)s_raw;                            // [RPB*THREADS]
    float (*s_warp)[RPB] = (float(*)[RPB])(s_raw + TILE_BYTES); // [8][RPB]
    float* s_tau = (float*)(s_raw + TILE_BYTES + 240);
    unsigned long long* s_mbar = (unsigned long long*)(s_raw + TILE_BYTES + 248);

    const int b   = blk >> 4;          // batch
    const int sub = blk & 15;          // sub-block within batch
    unsigned*           const cnt = &g_count[b * CPAD];
    unsigned long long* const syn = &g_sync[b * SPAD];
    const unsigned mbar = smem_u32(s_mbar);
    const unsigned tile = smem_u32(s_tile);

    // base_gen read precedes this block's first publish -> race-free.
    unsigned base_gen = 0;
    if (tid == 0) {
        base_gen = (unsigned)(*(volatile unsigned long long*)syn >> 32);
        asm volatile("mbarrier.init.shared.b64 [%0], 1;" :: "r"(mbar) : "memory");
    }
    __syncthreads();

    const size_t row_base = ((size_t)b * NT * NC + (size_t)sub * RPB) * HW_;

    // Prologue: TMA bulk load of x[0] (one instruction).
    if (tid == 0) tma_tile_load(tile, x + row_base, mbar);

    float tau = 0.5f;                  // TAU0
    float4 mem[RPB];
    #pragma unroll
    for (int i = 0; i < RPB; i++) mem[i] = make_float4(0.f, 0.f, 0.f, 0.f);

    for (int t = 0; t < NT; t++) {
        float4* op = (float4*)(out + row_base + (size_t)t * NC * HW_);
        const bool need_tau = (t < NT - 1);

        // ---- 0) wait for this step's tile (free in steady state) ----
        {
            const unsigned parity = (unsigned)(t & 1);
            unsigned done;
            asm volatile(
                "{\n\t.reg .pred p;\n\t"
                "mbarrier.try_wait.parity.acquire.cta.shared::cta.b64 p, [%1], %2;\n\t"
                "selp.b32 %0, 1, 0, p;\n\t}"
                : "=r"(done) : "r"(mbar), "r"(parity) : "memory");
            if (!done) {
                asm volatile(
                    "{\n\t.reg .pred P1;\n\t"
                    "LW%=:\n\t"
                    "mbarrier.try_wait.parity.acquire.cta.shared::cta.b64 P1, [%0], %1, 0x989680;\n\t"
                    "@P1 bra.uni LD%=;\n\t"
                    "bra.uni LW%=;\n\t"
                    "LD%=:\n\t}"
                    :: "r"(mbar), "r"(parity) : "memory");
            }
        }

        // ---- 1) FMA consumption pass (reads the whole tile). Values and
        //         order identical to R10/R14. ----
        float part[RPB];
        #pragma unroll
        for (int i = 0; i < RPB; i++) {
            float4 xv = s_tile[i * THREADS + tid];
            float4 m = mem[i];
            m.x = __fadd_rn(__fmul_rn(m.x, tau), xv.x);
            m.y = __fadd_rn(__fmul_rn(m.y, tau), xv.y);
            m.z = __fadd_rn(__fmul_rn(m.z, tau), xv.z);
            m.w = __fadd_rn(__fmul_rn(m.w, tau), xv.w);
            mem[i] = m;
            part[i] = (m.x + m.y) + (m.z + m.w);
        }

        __syncthreads();   // sync#1: tile fully READ -> safe to overwrite

        // ---- 2) kick TMA for x[t+1] IMMEDIATELY (before the reduce) ----
        if (t + 1 < NT && tid == 0)
            tma_tile_load(tile, x + row_base + (size_t)(t + 1) * NC * HW_, mbar);

        if (need_tau) {
            // ---- 3) shfl-reduce (identical order), overlaps the TMA ----
            #pragma unroll
            for (int i = 0; i < RPB; i++) {
                float v = part[i];
                v += __shfl_xor_sync(0xffffffffu, v, 16);
                v += __shfl_xor_sync(0xffffffffu, v, 8);
                v += __shfl_xor_sync(0xffffffffu, v, 4);
                v += __shfl_xor_sync(0xffffffffu, v, 2);
                v += __shfl_xor_sync(0xffffffffu, v, 1);
                if (lane == 0) s_warp[warp][i] = v;
            }
            __syncthreads();   // sync#2: s_warp complete

            // ---- 4) publish this block's 8 channel sums (== R10) ----
            if (tid < RPB) {
                float s = 0.f;
                #pragma unroll
                for (int w = 0; w < 8; w++) s += s_warp[w][tid];
                __stcg(&g_sums[b * NC + sub * RPB + tid], s);
                red_release_add(cnt, 1u);
            }
        }

        // ---- 5) spike + output + soft reset (overlaps TMA + coord MLP) ----
        #pragma unroll
        for (int i = 0; i < RPB; i++) {
            float4 m = mem[i];
            float4 sp;
            sp.x = (m.x > 1.0f) ? 1.0f : 0.0f;
            sp.y = (m.y > 1.0f) ? 1.0f : 0.0f;
            sp.z = (m.z > 1.0f) ? 1.0f : 0.0f;
            sp.w = (m.w > 1.0f) ? 1.0f : 0.0f;
            __stcs(op + i * THREADS + tid, sp);
            m.x = (m.x > 1.0f) ? 0.0f : m.x;
            m.y = (m.y > 1.0f) ? 0.0f : m.y;
            m.z = (m.z > 1.0f) ? 0.0f : m.z;
            m.w = (m.w > 1.0f) ? 0.0f : m.w;
            mem[i] = m;
        }

        if (!need_tau) break;

        // ---- 6) single poll: generation + tau arrive together ----
        if (tid == 0) {
            unsigned tgt = base_gen + (unsigned)(t + 1);
            unsigned long long v;
            do {
                v = ld_acquire_u64(syn);
            } while ((int)((unsigned)(v >> 32) - tgt) < 0);
            *s_tau = __uint_as_float((unsigned)v);
        }
        __syncthreads();
        tau = *s_tau;
    }

    // Invalidate the mbarrier so the next graph replay re-inits cleanly.
    __syncthreads();
    if (tid == 0)
        asm volatile("mbarrier.inval.shared.b64 [%0];" :: "r"(mbar) : "memory");
}

extern "C" void kernel_launch(void* const* d_in, const int* in_sizes, int n_in,
                              void* d_out, int out_size)
{
    const float* x  = (const float*)d_in[0];
    const float* w1 = (const float*)d_in[1];
    const float* b1 = (const float*)d_in[2];
    const float* w2 = (const float*)d_in[3];
    const float* b2 = (const float*)d_in[4];
    float* out = (float*)d_out;

    lif_kernel<<<NBLOCKS, THREADS>>>(x, w1, b1, w2, b2, out);
}

// round 16
// speedup vs baseline: 1.4785x; 1.1515x over previous
#include <cuda_runtime.h>
#include <cstdint>

// DynamicLIF persistent kernel for GB300 (sm_103a), round 16.
// Base = R15 (64.2us bench / 57.6us ncu: TMA bulk tile loads, coordinator
// MLP, packed gen|tau release). CHANGE: the rendezvous is pipelined ONE
// FULL STEP ahead using the R5-validated factorization (rel_err 0.0):
//     S(t) = tau_t * P(t-1) + X(t)
// P(t) (post-reset mem sums) and X(t+1) (raw sums of the TMA-landed next
// tile) are both tau_{t+1}-free, so blocks publish the pair DURING step t
// and the coordinator (which knows tau_{t+1} locally from its previous
// iteration) releases tau_{t+2} a full step early. The publish->MLP->
// release->wakeup chain (~1.9us/step) leaves the critical path entirely.
// Rounds: r=0 = X(0) (early step 0); r=1..6 = (P(r-1), X(r)) (late step
// r-1). 128 count-releases per round; round buffers double-buffered by
// r&1 (publisher of round r+2 must first acquire gen r+1, which the
// coordinator releases only after consuming round r -> no overwrite race).
// All reduction orders and coordinator arithmetic byte-identical to
// R5/R10/R15 paths (each benched rel_err 0.0).

#define NB 32          // batch
#define NT 8           // time steps
#define NC 128         // channels
#define HW_ 1024       // H*W
#define CR 32          // C / red
#define THREADS 256
#define RPB 8          // channel rows per block
#define BPB 16         // streaming blocks per batch
#define NSTREAM (NB * BPB)       // 512
#define NBLOCKS (NSTREAM + NB)   // 544 (32 coordinators)
#define PUBS (BPB * RPB)         // 128 count-releases per round
#define CPAD 64        // 256B stride for g_count (unsigned)
#define SPAD 32        // 256B stride for g_sync (u64)
#define TILE_BYTES (RPB * THREADS * 16)   // 32768

__device__ float              g_P[2][NB * NC];   // post-reset sums, round r&1
__device__ float              g_X[2][NB * NC];   // raw x sums, round r&1
__device__ unsigned           g_count[NB * CPAD]; // zero at launch; coord resets at end
__device__ unsigned long long g_sync[NB * SPAD];  // (gen<<32)|tau_bits, monotonic gen

__device__ __forceinline__ unsigned ld_acquire_u32(const unsigned* p) {
    unsigned v;
    asm volatile("ld.acquire.gpu.global.u32 %0, [%1];" : "=r"(v) : "l"(p));
    return v;
}
__device__ __forceinline__ unsigned long long ld_acquire_u64(const unsigned long long* p) {
    unsigned long long v;
    asm volatile("ld.acquire.gpu.global.u64 %0, [%1];" : "=l"(v) : "l"(p));
    return v;
}
__device__ __forceinline__ void st_release_u64(unsigned long long* p, unsigned long long v) {
    asm volatile("st.release.gpu.global.u64 [%0], %1;" :: "l"(p), "l"(v));
}
__device__ __forceinline__ void red_release_add(unsigned* p, unsigned v) {
    asm volatile("red.release.gpu.global.add.u32 [%0], %1;" :: "l"(p), "r"(v));
}
__device__ __forceinline__ unsigned smem_u32(const void* p) {
    return (unsigned)__cvta_generic_to_shared(p);
}
__device__ __forceinline__ void tma_tile_load(unsigned tile, const float* src, unsigned mbar) {
    asm volatile("mbarrier.arrive.expect_tx.shared.b64 _, [%0], %1;"
                 :: "r"(mbar), "r"((unsigned)TILE_BYTES) : "memory");
    asm volatile("cp.async.bulk.shared::cta.global.mbarrier::complete_tx::bytes "
                 "[%0], [%1], %2, [%3];"
                 :: "r"(tile), "l"(src), "r"((unsigned)TILE_BYTES), "r"(mbar)
                 : "memory");
}
__device__ __forceinline__ void mbar_wait(unsigned mbar, unsigned parity) {
    unsigned done;
    asm volatile(
        "{\n\t.reg .pred p;\n\t"
        "mbarrier.try_wait.parity.acquire.cta.shared::cta.b64 p, [%1], %2;\n\t"
        "selp.b32 %0, 1, 0, p;\n\t}"
        : "=r"(done) : "r"(mbar), "r"(parity) : "memory");
    if (!done) {
        asm volatile(
            "{\n\t.reg .pred P1;\n\t"
            "LW%=:\n\t"
            "mbarrier.try_wait.parity.acquire.cta.shared::cta.b64 P1, [%0], %1, 0x989680;\n\t"
            "@P1 bra.uni LD%=;\n\t"
            "bra.uni LW%=;\n\t"
            "LD%=:\n\t}"
            :: "r"(mbar), "r"(parity) : "memory");
    }
}

__global__ void __launch_bounds__(THREADS, 4)
lif_kernel(const float* __restrict__ x,
           const float* __restrict__ w1,
           const float* __restrict__ b1,
           const float* __restrict__ w2,
           const float* __restrict__ b2,
           float* __restrict__ out)
{
    __shared__ __align__(128) char s_raw[TILE_BYTES + 768];

    const int tid = threadIdx.x;
    const int blk = blockIdx.x;
    const int lane = tid & 31;
    const int warp = tid >> 5;

    // ---------------- coordinator blocks (one per batch) ----------------
    if (blk >= NSTREAM) {
        float* s_w1t  = (float*)s_raw;              // [NC*CR] transposed
        float* s_mean = (float*)(s_raw + 16384);    // [NC]
        float* s_tn   = (float*)(s_raw + 16384 + 512);

        const int bb = blk - NSTREAM;
        unsigned*           cnt = &g_count[bb * CPAD];
        unsigned long long* syn = &g_sync[bb * SPAD];

        #pragma unroll
        for (int i = 0; i < (CR * NC) / THREADS; i++) {
            int idx = i * THREADS + tid;
            s_w1t[(idx & 127) * CR + (idx >> 7)] = w1[idx];
        }

        unsigned base_gen = 0;
        if (tid == 0) base_gen = (unsigned)(*(volatile unsigned long long*)syn >> 32);
        __syncthreads();

        float tauk = 0.0f;   // tau_k; unused at k==0
        #pragma unroll 1
        for (int k = 0; k < NT - 1; k++) {
            // Wait for round k (128 publishes).
            if (tid == 0) {
                unsigned tgt = (unsigned)PUBS * (unsigned)(k + 1);
                while (ld_acquire_u32(cnt) < tgt) { }
            }
            __syncthreads();   // acquire by t0 + barrier -> round data visible

            // S(k) = tau_k*P(k-1) + X(k)  (k==0: S=X). Same arithmetic and
            // order as R5 (benched rel_err 0.0).
            const int buf = k & 1;
            if (tid < NC) {
                float Xc = __ldcg(&g_X[buf][bb * NC + tid]);
                float Sc;
                if (k == 0) {
                    Sc = Xc;
                } else {
                    float Pc = __ldcg(&g_P[buf][bb * NC + tid]);
                    Sc = __fadd_rn(__fmul_rn(tauk, Pc), Xc);
                }
                s_mean[tid] = Sc * (1.0f / 1024.0f);
            }
            __syncthreads();
            if (tid < CR) {
                float acc = b1[tid];
                #pragma unroll
                for (int c = 0; c < NC; c++)
                    acc = fmaf(s_w1t[c * CR + tid], s_mean[c], acc);
                float e = fmaxf(acc, 0.0f);        // relu
                float p = e * w2[tid];
                p += __shfl_xor_sync(0xffffffffu, p, 16);
                p += __shfl_xor_sync(0xffffffffu, p, 8);
                p += __shfl_xor_sync(0xffffffffu, p, 4);
                p += __shfl_xor_sync(0xffffffffu, p, 2);
                p += __shfl_xor_sync(0xffffffffu, p, 1);
                if (tid == 0) {
                    float z = p + b2[0];
                    float tn = 1.0f / (1.0f + expf(-z));   // sigmoid = tau_{k+1}
                    *s_tn = tn;
                    unsigned long long v =
                        ((unsigned long long)(base_gen + (unsigned)(k + 1)) << 32)
                        | (unsigned long long)__float_as_uint(tn);
                    st_release_u64(syn, v);   // gen + tau in one word
                }
            }
            __syncthreads();
            tauk = *s_tn;      // tau_{k+1} for the next iteration's S
        }
        if (tid == 0) *(volatile unsigned*)cnt = 0;   // replay-safe reset
        return;
    }

    // ---------------- streaming blocks ----------------
    float4* s_tile = (float4*)s_raw;                             // [RPB*THREADS]
    float (*s_warpP)[RPB] = (float(*)[RPB])(s_raw + TILE_BYTES);       // [8][8]
    float (*s_warpX)[RPB] = (float(*)[RPB])(s_raw + TILE_BYTES + 256); // [8][8]
    float* s_tau = (float*)(s_raw + TILE_BYTES + 512);
    unsigned long long* s_mbar = (unsigned long long*)(s_raw + TILE_BYTES + 520);

    const int b   = blk >> 4;          // batch
    const int sub = blk & 15;          // sub-block within batch
    unsigned*           const cnt = &g_count[b * CPAD];
    unsigned long long* const syn = &g_sync[b * SPAD];
    const unsigned mbar = smem_u32(s_mbar);
    const unsigned tile = smem_u32(s_tile);

    // base_gen read precedes this block's first publish; no release can
    // precede round 0's 128 publishes -> race-free across startup skew AND
    // graph replays.
    unsigned base_gen = 0;
    if (tid == 0) {
        base_gen = (unsigned)(*(volatile unsigned long long*)syn >> 32);
        asm volatile("mbarrier.init.shared.b64 [%0], 1;" :: "r"(mbar) : "memory");
    }
    __syncthreads();

    const size_t row_base = ((size_t)b * NT * NC + (size_t)sub * RPB) * HW_;

    // Prologue: TMA tile 0; on arrival publish X(0) (round 0, buffer 0).
    if (tid == 0) tma_tile_load(tile, x + row_base, mbar);
    mbar_wait(mbar, 0u);
    {
        float pX[RPB];
        #pragma unroll
        for (int i = 0; i < RPB; i++) {
            float4 xv = s_tile[i * THREADS + tid];
            float v = (xv.x + xv.y) + (xv.z + xv.w);
            v += __shfl_xor_sync(0xffffffffu, v, 16);
            v += __shfl_xor_sync(0xffffffffu, v, 8);
            v += __shfl_xor_sync(0xffffffffu, v, 4);
            v += __shfl_xor_sync(0xffffffffu, v, 2);
            v += __shfl_xor_sync(0xffffffffu, v, 1);
            pX[i] = v;
        }
        if (lane == 0) {
            #pragma unroll
            for (int i = 0; i < RPB; i++) s_warpX[warp][i] = pX[i];
        }
    }
    __syncthreads();
    if (tid < RPB) {
        float s = 0.f;
        #pragma unroll
        for (int w = 0; w < 8; w++) s += s_warpX[w][tid];
        __stcg(&g_X[0][b * NC + sub * RPB + tid], s);
        red_release_add(cnt, 1u);      // round 0
    }

    float tau = 0.5f;                  // TAU0
    float4 mem[RPB];
    #pragma unroll
    for (int i = 0; i < RPB; i++) mem[i] = make_float4(0.f, 0.f, 0.f, 0.f);

    for (int t = 0; t < NT; t++) {
        float4* op = (float4*)(out + row_base + (size_t)t * NC * HW_);
        const bool pub   = (t <= NT - 3);   // rounds 1..6 at steps 0..5
        const bool nextt = (t < NT - 1);

        // ---- 1) FMA pass over tile t (already in smem; waited in the
        //         prologue for t=0, or late in step t-1 otherwise). ----
        float part[RPB];
        #pragma unroll
        for (int i = 0; i < RPB; i++) {
            float4 xv = s_tile[i * THREADS + tid];
            float4 m = mem[i];
            m.x = __fadd_rn(__fmul_rn(m.x, tau), xv.x);
            m.y = __fadd_rn(__fmul_rn(m.y, tau), xv.y);
            m.z = __fadd_rn(__fmul_rn(m.z, tau), xv.z);
            m.w = __fadd_rn(__fmul_rn(m.w, tau), xv.w);
            mem[i] = m;
        }
        __syncthreads();   // tile t fully consumed -> safe to overwrite

        // ---- 2) TMA tile t+1 (one instruction) ----
        if (nextt && tid == 0)
            tma_tile_load(tile, x + row_base + (size_t)(t + 1) * NC * HW_, mbar);

        // ---- 3) spike + output + soft reset; P(t) partials ----
        #pragma unroll
        for (int i = 0; i < RPB; i++) {
            float4 m = mem[i];
            float4 sp;
            sp.x = (m.x > 1.0f) ? 1.0f : 0.0f;
            sp.y = (m.y > 1.0f) ? 1.0f : 0.0f;
            sp.z = (m.z > 1.0f) ? 1.0f : 0.0f;
            sp.w = (m.w > 1.0f) ? 1.0f : 0.0f;
            __stcs(op + i * THREADS + tid, sp);
            m.x = (m.x > 1.0f) ? 0.0f : m.x;
            m.y = (m.y > 1.0f) ? 0.0f : m.y;
            m.z = (m.z > 1.0f) ? 0.0f : m.z;
            m.w = (m.w > 1.0f) ? 0.0f : m.w;
            mem[i] = m;
            part[i] = (m.x + m.y) + (m.z + m.w);
        }

        if (pub) {
            // P(t) shfl-reduce (identical order).
            #pragma unroll
            for (int i = 0; i < RPB; i++) {
                float v = part[i];
                v += __shfl_xor_sync(0xffffffffu, v, 16);
                v += __shfl_xor_sync(0xffffffffu, v, 8);
                v += __shfl_xor_sync(0xffffffffu, v, 4);
                v += __shfl_xor_sync(0xffffffffu, v, 2);
                v += __shfl_xor_sync(0xffffffffu, v, 1);
                if (lane == 0) s_warpP[warp][i] = v;
            }
        }

        if (!nextt) break;   // t == 7: done after stores

        // ---- 4) wait tile t+1, then X(t+1) partials from it ----
        mbar_wait(mbar, (unsigned)((t + 1) & 1));

        if (pub) {
            #pragma unroll
            for (int i = 0; i < RPB; i++) {
                float4 xv = s_tile[i * THREADS + tid];
                float v = (xv.x + xv.y) + (xv.z + xv.w);
                v += __shfl_xor_sync(0xffffffffu, v, 16);
                v += __shfl_xor_sync(0xffffffffu, v, 8);
                v += __shfl_xor_sync(0xffffffffu, v, 4);
                v += __shfl_xor_sync(0xffffffffu, v, 2);
                v += __shfl_xor_sync(0xffffffffu, v, 1);
                if (lane == 0) s_warpX[warp][i] = v;
            }
            __syncthreads();   // s_warpP + s_warpX complete

            // ---- 5) publish round t+1: (P(t), X(t+1)) into buffer (t+1)&1 ----
            if (tid < RPB) {
                const int buf = (t + 1) & 1;
                float sp_ = 0.f, sx_ = 0.f;
                #pragma unroll
                for (int w = 0; w < 8; w++) { sp_ += s_warpP[w][tid]; sx_ += s_warpX[w][tid]; }
                __stcg(&g_P[buf][b * NC + sub * RPB + tid], sp_);
                __stcg(&g_X[buf][b * NC + sub * RPB + tid], sx_);
                red_release_add(cnt, 1u);
            }
        }

        // ---- 6) poll tau_{t+1}: released a full step ago in steady state ----
        if (tid == 0) {
            unsigned tgt = base_gen + (unsigned)(t + 1);
            unsigned long long v;
            do {
                v = ld_acquire_u64(syn);
            } while ((int)((unsigned)(v >> 32) - tgt) < 0);
            *s_tau = __uint_as_float((unsigned)v);
        }
        __syncthreads();
        tau = *s_tau;
    }

    // Invalidate the mbarrier so the next graph replay re-inits cleanly.
    __syncthreads();
    if (tid == 0)
        asm volatile("mbarrier.inval.shared.b64 [%0];" :: "r"(mbar) : "memory");
}

extern "C" void kernel_launch(void* const* d_in, const int* in_sizes, int n_in,
                              void* d_out, int out_size)
{
    const float* x  = (const float*)d_in[0];
    const float* w1 = (const float*)d_in[1];
    const float* b1 = (const float*)d_in[2];
    const float* w2 = (const float*)d_in[3];
    const float* b2 = (const float*)d_in[4];
    float* out = (float*)d_out;

    lif_kernel<<<NBLOCKS, THREADS>>>(x, w1, b1, w2, b2, out);
}